// round 1
// baseline (speedup 1.0000x reference)
#include <cuda_runtime.h>
#include <math.h>

// Problem constants (fixed by the reference)
#define DIM     512
#define MNODES  90
#define KKEEP   45
#define TEN_LC  23
#define TEN_RC  22
#define MAXN    184320   // B*M = 2048*90
#define MAXBK   92160    // B*K = 2048*45

// Scratch (static device globals — no allocation allowed)
__device__ float g_score[MAXN];
__device__ int   g_perm[MAXBK];
__device__ int   g_node_map[MAXN];
__device__ float g_inv_wnorm;

// ---------------------------------------------------------------------------
// Kernel 0: 1/||w||
// ---------------------------------------------------------------------------
__global__ void k_wnorm(const float* __restrict__ w) {
    __shared__ float red[512];
    int t = threadIdx.x;
    float v = w[t];
    red[t] = v * v;
    __syncthreads();
    for (int s = 256; s > 0; s >>= 1) {
        if (t < s) red[t] += red[t + s];
        __syncthreads();
    }
    if (t == 0) g_inv_wnorm = rsqrtf(red[0]);
}

// ---------------------------------------------------------------------------
// Kernel 1: score[i] = tanh(dot(x[i], w) / ||w||). One warp per row.
// ---------------------------------------------------------------------------
__global__ void k_score(const float4* __restrict__ x4) {
    __shared__ float4 ws[DIM / 4];
    extern __shared__ char dummy[];
    int t = threadIdx.x;
    // weight is loaded via const path from global each block? -> load from global w.
    // (w passed via constant folded below: we stash it in ws from global param)
    // NOTE: weight pointer passed through ws via separate param version below.
    (void)dummy; (void)ws; (void)t; (void)x4;
}

// Real score kernel (with weight param)
__global__ void k_score2(const float4* __restrict__ x4, const float4* __restrict__ w4) {
    __shared__ float4 ws[DIM / 4];
    int t = threadIdx.x;
    if (t < DIM / 4) ws[t] = w4[t];
    __syncthreads();
    int warp = t >> 5, lane = t & 31;
    int row = blockIdx.x * 8 + warp;
    const float4* xr = x4 + (size_t)row * (DIM / 4);
    float s = 0.f;
#pragma unroll
    for (int i = 0; i < 4; i++) {
        float4 a = xr[lane + 32 * i];
        float4 b = ws[lane + 32 * i];
        s += a.x * b.x + a.y * b.y + a.z * b.z + a.w * b.w;
    }
#pragma unroll
    for (int o = 16; o; o >>= 1) s += __shfl_xor_sync(0xffffffffu, s, o);
    if (lane == 0) g_score[row] = tanhf(s * g_inv_wnorm);
}

// ---------------------------------------------------------------------------
// Kernel 2: per-graph descending sort (bitonic, 128 padded) + category select.
// Writes: perm_lab, perm, batch_out sections of output; g_perm, g_node_map.
// ---------------------------------------------------------------------------
__global__ void k_pool(float* __restrict__ out_batch,
                       float* __restrict__ out_perm,
                       float* __restrict__ out_permlab) {
    __shared__ float sk[128];
    __shared__ int   sv[128];
    int b = blockIdx.x, t = threadIdx.x;

    if (t < MNODES) {
        sk[t] = g_score[b * MNODES + t];
        g_node_map[b * MNODES + t] = -1;   // default: node not selected
    } else {
        sk[t] = -INFINITY;                  // padding sorts to the end
    }
    sv[t] = t;
    __syncthreads();

    // Bitonic sort, descending by key, tiebreak ascending id (strict total order)
    for (int size = 2; size <= 128; size <<= 1) {
        for (int stride = size >> 1; stride > 0; stride >>= 1) {
            int j = t ^ stride;
            if (j > t) {
                float ki = sk[t], kj = sk[j];
                int   vi = sv[t], vj = sv[j];
                bool pre = (ki > kj) || (ki == kj && vi < vj); // i precedes j (desc)
                bool desc = ((t & size) == 0);
                if (desc ? !pre : pre) {
                    sk[t] = kj; sk[j] = ki;
                    sv[t] = vj; sv[j] = vi;
                }
            }
            __syncthreads();
        }
    }

    // perm_lab: global ids in score-sorted order
    if (t < MNODES)
        out_permlab[b * MNODES + t] = (float)(b * MNODES + sv[t]);
    __syncthreads();

    // Category selection: first TEN_LC even local ids, then TEN_RC odd, in order
    if (t == 0) {
        int ce = 0, co = 0;
        for (int p = 0; p < MNODES && (ce < TEN_LC || co < TEN_RC); p++) {
            int id = sv[p];
            int slot;
            if ((id & 1) == 0) {
                if (ce >= TEN_LC) continue;
                slot = ce++;
            } else {
                if (co >= TEN_RC) continue;
                slot = TEN_LC + co++;
            }
            int g = b * MNODES + id;
            int j = b * KKEEP + slot;
            g_perm[j]     = g;
            g_node_map[g] = j;
            out_perm[j]   = (float)g;
            out_batch[j]  = (float)b;
        }
    }
}

// ---------------------------------------------------------------------------
// Kernel 3: x_out[j] = x[perm[j]] * score[perm[j]]. One block per output row.
// ---------------------------------------------------------------------------
__global__ void k_gather(const float4* __restrict__ x4, float4* __restrict__ out4) {
    int j = blockIdx.x;
    int g = g_perm[j];
    float sc = g_score[g];
    const float4* src = x4 + (size_t)g * (DIM / 4);
    float4*       dst = out4 + (size_t)j * (DIM / 4);
    float4 a = src[threadIdx.x];
    a.x *= sc; a.y *= sc; a.z *= sc; a.w *= sc;
    dst[threadIdx.x] = a;
}

// ---------------------------------------------------------------------------
// Kernel 4: edge relabel + mask
// ---------------------------------------------------------------------------
__global__ void k_edges(const int* __restrict__ ei, long long E,
                        float* __restrict__ out_edge,   // [2, E]
                        float* __restrict__ out_mask) { // [E]
    long long e = blockIdx.x * (long long)blockDim.x + threadIdx.x;
    if (e >= E) return;
    int r = g_node_map[ei[e]];
    int c = g_node_map[ei[E + e]];
    bool m = (r >= 0) && (c >= 0);
    out_edge[e]     = m ? (float)r : -1.f;
    out_edge[E + e] = m ? (float)c : -1.f;
    out_mask[e]     = m ? 1.f : 0.f;
}

// ---------------------------------------------------------------------------
// Launch
// ---------------------------------------------------------------------------
extern "C" void kernel_launch(void* const* d_in, const int* in_sizes, int n_in,
                              void* d_out, int out_size) {
    const float* x  = (const float*)d_in[0];
    const float* w  = (const float*)d_in[1];
    const int*   ei = (const int*)d_in[2];
    // d_in[3] = batch (unused; batch[perm[j]] == graph id by construction)

    int N = in_sizes[0] / DIM;     // 184320
    int B = N / MNODES;            // 2048
    long long E = (long long)in_sizes[2] / 2;

    float* out = (float*)d_out;
    // Output packing: x_out | new_edge_index[2,E] | batch_out | perm | perm_lab | edge_mask
    size_t off_edge    = (size_t)B * KKEEP * DIM;
    size_t off_batch   = off_edge + 2 * (size_t)E;
    size_t off_perm    = off_batch + (size_t)B * KKEEP;
    size_t off_permlab = off_perm + (size_t)B * KKEEP;
    size_t off_mask    = off_permlab + (size_t)N;

    k_wnorm<<<1, 512>>>(w);
    k_score2<<<N / 8, 256>>>((const float4*)x, (const float4*)w);
    k_pool<<<B, 128>>>(out + off_batch, out + off_perm, out + off_permlab);
    k_gather<<<B * KKEEP, 128>>>((const float4*)x, (float4*)out);
    int eb = (int)((E + 255) / 256);
    k_edges<<<eb, 256>>>(ei, E, out + off_edge, out + off_mask);
}

// round 2
// speedup vs baseline: 1.1807x; 1.1807x over previous
#include <cuda_runtime.h>
#include <math.h>

#define DIM     512
#define MNODES  90
#define KKEEP   45
#define TEN_LC  23
#define TEN_RC  22
#define MAXN    184320   // B*M = 2048*90

__device__ int g_node_map[MAXN];

// ---------------------------------------------------------------------------
// Fused: score -> sort -> category select -> gather. One block per graph.
// ---------------------------------------------------------------------------
__global__ __launch_bounds__(512) void k_fused(
    const float4* __restrict__ x4, const float4* __restrict__ w4,
    float4* __restrict__ out_x,
    float* __restrict__ out_batch, float* __restrict__ out_perm,
    float* __restrict__ out_permlab)
{
    __shared__ float4 ws[DIM / 4];
    __shared__ float  sk[128];
    __shared__ int    sv[128];
    __shared__ float  red[16];
    __shared__ int    warp_tot[4];
    __shared__ int    sel_gid[KKEEP];
    __shared__ float  sel_sc[KKEEP];
    __shared__ float  s_inv;

    const int t = threadIdx.x, b = blockIdx.x;
    const int warp = t >> 5, lane = t & 31;

    // --- load weight, compute 1/||w|| (block reduce) ---
    float4 wv = make_float4(0.f, 0.f, 0.f, 0.f);
    if (t < DIM / 4) { wv = w4[t]; ws[t] = wv; }
    float ss = wv.x * wv.x + wv.y * wv.y + wv.z * wv.z + wv.w * wv.w;
#pragma unroll
    for (int o = 16; o; o >>= 1) ss += __shfl_xor_sync(0xffffffffu, ss, o);
    if (lane == 0) red[warp] = ss;

    if (t >= MNODES && t < 128) sk[t] = -INFINITY;   // sort padding
    if (t < 128) sv[t] = t;
    if (t < MNODES) g_node_map[b * MNODES + t] = -1;
    __syncthreads();
    if (t == 0) {
        float a = 0.f;
#pragma unroll
        for (int i = 0; i < 16; i++) a += red[i];
        s_inv = rsqrtf(a);
    }
    __syncthreads();

    // --- scores: one warp per row ---
    for (int r = warp; r < MNODES; r += 16) {
        const float4* xr = x4 + (size_t)(b * MNODES + r) * (DIM / 4);
        float s = 0.f;
#pragma unroll
        for (int i = 0; i < 4; i++) {
            float4 a = xr[lane + 32 * i];
            float4 wb = ws[lane + 32 * i];
            s += a.x * wb.x + a.y * wb.y + a.z * wb.z + a.w * wb.w;
        }
#pragma unroll
        for (int o = 16; o; o >>= 1) s += __shfl_xor_sync(0xffffffffu, s, o);
        if (lane == 0) sk[r] = tanhf(s * s_inv);
    }
    __syncthreads();

    // --- bitonic sort, descending key, ascending-id tiebreak ---
    for (int size = 2; size <= 128; size <<= 1) {
        for (int stride = size >> 1; stride > 0; stride >>= 1) {
            if (t < 128) {
                int j = t ^ stride;
                if (j > t) {
                    float ki = sk[t], kj = sk[j];
                    int   vi = sv[t], vj = sv[j];
                    bool pre  = (ki > kj) || (ki == kj && vi < vj);
                    bool desc = ((t & size) == 0);
                    if (desc ? !pre : pre) {
                        sk[t] = kj; sk[j] = ki;
                        sv[t] = vj; sv[j] = vi;
                    }
                }
            }
            __syncthreads();
        }
    }

    if (t < MNODES)
        out_permlab[b * MNODES + t] = (float)(b * MNODES + sv[t]);

    // --- category selection via ballot prefix scan over sorted parity ---
    int flag = 0, excl = 0;
    if (t < 128) flag = (t < MNODES && ((sv[t] & 1) == 0)) ? 1 : 0;
    if (warp < 4) {
        unsigned ball = __ballot_sync(0xffffffffu, flag);
        excl = __popc(ball & ((1u << lane) - 1u));
        if (lane == 0) warp_tot[warp] = __popc(ball);
    }
    __syncthreads();
    if (t < MNODES) {
        int base = 0;
        for (int i = 0; i < warp; i++) base += warp_tot[i];
        int ev = base + excl;      // # evens among sorted positions < t
        int od = t - ev;           // # odds among sorted positions < t
        int slot = -1;
        if (flag) { if (ev < TEN_LC) slot = ev; }
        else      { if (od < TEN_RC) slot = TEN_LC + od; }
        if (slot >= 0) {
            int gid = b * MNODES + sv[t];
            int j   = b * KKEEP + slot;
            sel_gid[slot] = gid;
            sel_sc[slot]  = sk[t];
            g_node_map[gid] = j;
            out_perm[j]  = (float)gid;
            out_batch[j] = (float)b;
        }
    }
    __syncthreads();

    // --- gather selected rows (hot in L2), scale, store ---
    for (int slot = warp; slot < KKEEP; slot += 16) {
        int gid  = sel_gid[slot];
        float sc = sel_sc[slot];
        const float4* src = x4 + (size_t)gid * (DIM / 4);
        float4*       dst = out_x + (size_t)(b * KKEEP + slot) * (DIM / 4);
#pragma unroll
        for (int i = 0; i < 4; i++) {
            float4 a = src[lane + 32 * i];
            a.x *= sc; a.y *= sc; a.z *= sc; a.w *= sc;
            dst[lane + 32 * i] = a;
        }
    }
}

// ---------------------------------------------------------------------------
// Edge relabel + mask, 4 edges per thread
// ---------------------------------------------------------------------------
__global__ void k_edges(const int4* __restrict__ ei0, const int4* __restrict__ ei1,
                        long long E4,
                        float4* __restrict__ oe0, float4* __restrict__ oe1,
                        float4* __restrict__ om)
{
    long long i = blockIdx.x * (long long)blockDim.x + threadIdx.x;
    if (i >= E4) return;
    int4 r4 = ei0[i];
    int4 c4 = ei1[i];
    int r0 = g_node_map[r4.x], c0 = g_node_map[c4.x];
    int r1 = g_node_map[r4.y], c1 = g_node_map[c4.y];
    int r2 = g_node_map[r4.z], c2 = g_node_map[c4.z];
    int r3 = g_node_map[r4.w], c3 = g_node_map[c4.w];
    bool m0 = (r0 >= 0) && (c0 >= 0);
    bool m1 = (r1 >= 0) && (c1 >= 0);
    bool m2 = (r2 >= 0) && (c2 >= 0);
    bool m3 = (r3 >= 0) && (c3 >= 0);
    oe0[i] = make_float4(m0 ? (float)r0 : -1.f, m1 ? (float)r1 : -1.f,
                         m2 ? (float)r2 : -1.f, m3 ? (float)r3 : -1.f);
    oe1[i] = make_float4(m0 ? (float)c0 : -1.f, m1 ? (float)c1 : -1.f,
                         m2 ? (float)c2 : -1.f, m3 ? (float)c3 : -1.f);
    om[i]  = make_float4(m0 ? 1.f : 0.f, m1 ? 1.f : 0.f,
                         m2 ? 1.f : 0.f, m3 ? 1.f : 0.f);
}

// ---------------------------------------------------------------------------
extern "C" void kernel_launch(void* const* d_in, const int* in_sizes, int n_in,
                              void* d_out, int out_size) {
    const float* x  = (const float*)d_in[0];
    const float* w  = (const float*)d_in[1];
    const int*   ei = (const int*)d_in[2];

    int N = in_sizes[0] / DIM;         // 184320
    int B = N / MNODES;                // 2048
    long long E = (long long)in_sizes[2] / 2;

    float* out = (float*)d_out;
    size_t off_edge    = (size_t)B * KKEEP * DIM;
    size_t off_batch   = off_edge + 2 * (size_t)E;
    size_t off_perm    = off_batch + (size_t)B * KKEEP;
    size_t off_permlab = off_perm + (size_t)B * KKEEP;
    size_t off_mask    = off_permlab + (size_t)N;

    k_fused<<<B, 512>>>((const float4*)x, (const float4*)w,
                        (float4*)out,
                        out + off_batch, out + off_perm, out + off_permlab);

    long long E4 = E / 4;
    int eb = (int)((E4 + 255) / 256);
    k_edges<<<eb, 256>>>((const int4*)ei, (const int4*)(ei + E), E4,
                         (float4*)(out + off_edge),
                         (float4*)(out + off_edge + E),
                         (float4*)(out + off_mask));
}

// round 3
// speedup vs baseline: 1.3030x; 1.1036x over previous
#include <cuda_runtime.h>
#include <math.h>

#define DIM     512
#define MNODES  90
#define KKEEP   45
#define TEN_LC  23
#define TEN_RC  22
#define MAXN    184320   // B*M = 2048*90

// Per-node slot-within-graph (0..44), 255 = not selected. 180 KB.
__device__ unsigned char g_slot8[MAXN];

// ---------------------------------------------------------------------------
// Fused: score -> sort -> category select -> gather. One block per graph.
// ---------------------------------------------------------------------------
__global__ __launch_bounds__(512) void k_fused(
    const float4* __restrict__ x4, const float4* __restrict__ w4,
    float4* __restrict__ out_x,
    float* __restrict__ out_batch, float* __restrict__ out_perm,
    float* __restrict__ out_permlab)
{
    __shared__ float4 ws[DIM / 4];
    __shared__ float  sk[128];
    __shared__ int    sv[128];
    __shared__ float  red[16];
    __shared__ int    warp_tot[4];
    __shared__ int    sel_gid[KKEEP];
    __shared__ float  sel_sc[KKEEP];
    __shared__ float  s_inv;

    const int t = threadIdx.x, b = blockIdx.x;
    const int warp = t >> 5, lane = t & 31;

    // --- load weight, compute 1/||w|| (block reduce) ---
    float4 wv = make_float4(0.f, 0.f, 0.f, 0.f);
    if (t < DIM / 4) { wv = w4[t]; ws[t] = wv; }
    float ss = wv.x * wv.x + wv.y * wv.y + wv.z * wv.z + wv.w * wv.w;
#pragma unroll
    for (int o = 16; o; o >>= 1) ss += __shfl_xor_sync(0xffffffffu, ss, o);
    if (lane == 0) red[warp] = ss;

    if (t >= MNODES && t < 128) sk[t] = -INFINITY;   // sort padding
    if (t < 128) sv[t] = t;
    if (t < MNODES) g_slot8[b * MNODES + t] = 255;   // default: dropped
    __syncthreads();
    if (t == 0) {
        float a = 0.f;
#pragma unroll
        for (int i = 0; i < 16; i++) a += red[i];
        s_inv = rsqrtf(a);
    }
    __syncthreads();

    // --- scores: one warp per row ---
    for (int r = warp; r < MNODES; r += 16) {
        const float4* xr = x4 + (size_t)(b * MNODES + r) * (DIM / 4);
        float s = 0.f;
#pragma unroll
        for (int i = 0; i < 4; i++) {
            float4 a = xr[lane + 32 * i];
            float4 wb = ws[lane + 32 * i];
            s += a.x * wb.x + a.y * wb.y + a.z * wb.z + a.w * wb.w;
        }
#pragma unroll
        for (int o = 16; o; o >>= 1) s += __shfl_xor_sync(0xffffffffu, s, o);
        if (lane == 0) sk[r] = tanhf(s * s_inv);
    }
    __syncthreads();

    // --- bitonic sort, descending key, ascending-id tiebreak ---
    for (int size = 2; size <= 128; size <<= 1) {
        for (int stride = size >> 1; stride > 0; stride >>= 1) {
            if (t < 128) {
                int j = t ^ stride;
                if (j > t) {
                    float ki = sk[t], kj = sk[j];
                    int   vi = sv[t], vj = sv[j];
                    bool pre  = (ki > kj) || (ki == kj && vi < vj);
                    bool desc = ((t & size) == 0);
                    if (desc ? !pre : pre) {
                        sk[t] = kj; sk[j] = ki;
                        sv[t] = vj; sv[j] = vi;
                    }
                }
            }
            __syncthreads();
        }
    }

    if (t < MNODES)
        out_permlab[b * MNODES + t] = (float)(b * MNODES + sv[t]);

    // --- category selection via ballot prefix scan over sorted parity ---
    int flag = 0, excl = 0;
    if (t < 128) flag = (t < MNODES && ((sv[t] & 1) == 0)) ? 1 : 0;
    if (warp < 4) {
        unsigned ball = __ballot_sync(0xffffffffu, flag);
        excl = __popc(ball & ((1u << lane) - 1u));
        if (lane == 0) warp_tot[warp] = __popc(ball);
    }
    __syncthreads();
    if (t < MNODES) {
        int base = 0;
        for (int i = 0; i < warp; i++) base += warp_tot[i];
        int ev = base + excl;      // # evens among sorted positions < t
        int od = t - ev;           // # odds among sorted positions < t
        int slot = -1;
        if (flag) { if (ev < TEN_LC) slot = ev; }
        else      { if (od < TEN_RC) slot = TEN_LC + od; }
        if (slot >= 0) {
            int gid = b * MNODES + sv[t];
            int j   = b * KKEEP + slot;
            sel_gid[slot] = gid;
            sel_sc[slot]  = sk[t];
            g_slot8[gid] = (unsigned char)slot;
            out_perm[j]  = (float)gid;
            out_batch[j] = (float)b;
        }
    }
    __syncthreads();

    // --- gather selected rows (hot in L2), scale, store ---
    for (int slot = warp; slot < KKEEP; slot += 16) {
        int gid  = sel_gid[slot];
        float sc = sel_sc[slot];
        const float4* src = x4 + (size_t)gid * (DIM / 4);
        float4*       dst = out_x + (size_t)(b * KKEEP + slot) * (DIM / 4);
#pragma unroll
        for (int i = 0; i < 4; i++) {
            float4 a = src[lane + 32 * i];
            a.x *= sc; a.y *= sc; a.z *= sc; a.w *= sc;
            dst[lane + 32 * i] = a;
        }
    }
}

// ---------------------------------------------------------------------------
// Edge relabel + mask. Persistent CTAs with the full slot table in SMEM.
// ---------------------------------------------------------------------------
__device__ __forceinline__ float map_id(const unsigned char* s_tab, int gid,
                                        bool& ok) {
    unsigned slot = s_tab[gid];
    ok = (slot != 255u);
    unsigned b = (unsigned)gid / 90u;
    return ok ? (float)(b * KKEEP + slot) : -1.f;
}

__global__ __launch_bounds__(512) void k_edges(
    const int4* __restrict__ ei0, const int4* __restrict__ ei1,
    long long E4,
    float4* __restrict__ oe0, float4* __restrict__ oe1,
    float4* __restrict__ om)
{
    extern __shared__ unsigned char s_tab[];   // MAXN bytes = 180 KB

    // cooperative table load (uint4 copies)
    const uint4* src = (const uint4*)g_slot8;
    uint4* dst = (uint4*)s_tab;
    for (int i = threadIdx.x; i < MAXN / 16; i += blockDim.x)
        dst[i] = src[i];
    __syncthreads();

    long long stride = (long long)gridDim.x * blockDim.x;
    for (long long i = blockIdx.x * (long long)blockDim.x + threadIdx.x;
         i < E4; i += stride) {
        int4 r4 = ei0[i];
        int4 c4 = ei1[i];
        bool mr0, mr1, mr2, mr3, mc0, mc1, mc2, mc3;
        float fr0 = map_id(s_tab, r4.x, mr0);
        float fr1 = map_id(s_tab, r4.y, mr1);
        float fr2 = map_id(s_tab, r4.z, mr2);
        float fr3 = map_id(s_tab, r4.w, mr3);
        float fc0 = map_id(s_tab, c4.x, mc0);
        float fc1 = map_id(s_tab, c4.y, mc1);
        float fc2 = map_id(s_tab, c4.z, mc2);
        float fc3 = map_id(s_tab, c4.w, mc3);
        bool m0 = mr0 && mc0, m1 = mr1 && mc1;
        bool m2 = mr2 && mc2, m3 = mr3 && mc3;
        oe0[i] = make_float4(m0 ? fr0 : -1.f, m1 ? fr1 : -1.f,
                             m2 ? fr2 : -1.f, m3 ? fr3 : -1.f);
        oe1[i] = make_float4(m0 ? fc0 : -1.f, m1 ? fc1 : -1.f,
                             m2 ? fc2 : -1.f, m3 ? fc3 : -1.f);
        om[i]  = make_float4(m0 ? 1.f : 0.f, m1 ? 1.f : 0.f,
                             m2 ? 1.f : 0.f, m3 ? 1.f : 0.f);
    }
}

// ---------------------------------------------------------------------------
extern "C" void kernel_launch(void* const* d_in, const int* in_sizes, int n_in,
                              void* d_out, int out_size) {
    const float* x  = (const float*)d_in[0];
    const float* w  = (const float*)d_in[1];
    const int*   ei = (const int*)d_in[2];

    int N = in_sizes[0] / DIM;         // 184320
    int B = N / MNODES;                // 2048
    long long E = (long long)in_sizes[2] / 2;

    float* out = (float*)d_out;
    size_t off_edge    = (size_t)B * KKEEP * DIM;
    size_t off_batch   = off_edge + 2 * (size_t)E;
    size_t off_perm    = off_batch + (size_t)B * KKEEP;
    size_t off_permlab = off_perm + (size_t)B * KKEEP;
    size_t off_mask    = off_permlab + (size_t)N;

    k_fused<<<B, 512>>>((const float4*)x, (const float4*)w,
                        (float4*)out,
                        out + off_batch, out + off_perm, out + off_permlab);

    static bool attr_set = false;
    if (!attr_set) {
        cudaFuncSetAttribute(k_edges, cudaFuncAttributeMaxDynamicSharedMemorySize,
                             MAXN);
        attr_set = true;
    }
    long long E4 = E / 4;
    k_edges<<<148, 512, MAXN>>>((const int4*)ei, (const int4*)(ei + E), E4,
                                (float4*)(out + off_edge),
                                (float4*)(out + off_edge + E),
                                (float4*)(out + off_mask));
}